// round 17
// baseline (speedup 1.0000x reference)
#include <cuda_runtime.h>

// ---------------------------------------------------------------------------
// TinyMixedHeteroLinkPredictor — round 17: R5 with ONE change — folded
// vectors move to smem, consumed AFTER gathers return (off the address
// path). Table pointers still selected by register SEL on scalar flags.
//
//   logit(e) = feat[tab_s(t)][src] . v_src[t] + feat[tab_d(t)][dst] . v_dst[t] + c[t]
//
// Evidence ledger:
//  * R3 edge kernel: 138.4 us @ 32 regs / 94% occ — same gather wavefronts &
//    sectors as fused -> fused's ~11 us deficit is register/occupancy only.
//  * R9 (-11 us) poison was LDS on the gather-ADDRESS path (pointer LUT).
//    Vector LDS on the consume path was never isolated. This round isolates it.
//  * Dead levers (measured): reg-capped occupancy (R9/10/11), stream bypass
//    (R12: DRAM 50%), L2 evict-last priority (R16: neutral).
//  * Kept from R5: 4 edges/thread int4 .cs streams, pairwise gather
//    consumption, .cs output, no forced launch bounds.
// ---------------------------------------------------------------------------

__global__ void fused_k(
    const float4* __restrict__ ax, const float4* __restrict__ px,
    const int* __restrict__ src, const int* __restrict__ dst,
    const int* __restrict__ typ, float* __restrict__ out, int E,
    const float* __restrict__ Wa, const float* __restrict__ ba,
    const float* __restrict__ Wp, const float* __restrict__ bp,
    const float* __restrict__ Ws, const float* __restrict__ bs,
    const int* __restrict__ fsrc, const int* __restrict__ fdst)
{
    __shared__ float4 s_vs[4];   // per-type src vector (flag pre-applied)
    __shared__ float4 s_vd[4];   // per-type dst vector
    __shared__ float  s_c[4];    // per-type constant
    __shared__ int    s_fs[4];   // per-type src-table flag (for ptr SEL)
    __shared__ int    s_fd[4];   // per-type dst-table flag

    if (threadIdx.x == 0) {
        float vas[4], vps[4], vad[4], vpd[4];
#pragma unroll
        for (int j = 0; j < 4; j++) {
            float a = 0.f, p = 0.f, ad = 0.f, pd = 0.f;
#pragma unroll
            for (int i = 0; i < 4; i++) {
                float wsi = Ws[i], wsd = Ws[4 + i];
                float wa = Wa[i * 4 + j], wp = Wp[i * 4 + j];
                a  += wsi * wa;  p  += wsi * wp;
                ad += wsd * wa;  pd += wsd * wp;
            }
            vas[j] = a; vps[j] = p; vad[j] = ad; vpd[j] = pd;
        }
        float cas = 0.f, cps = 0.f, cad = 0.f, cpd = 0.f;
#pragma unroll
        for (int i = 0; i < 4; i++) {
            cas += Ws[i]     * ba[i];
            cps += Ws[i]     * bp[i];
            cad += Ws[4 + i] * ba[i];
            cpd += Ws[4 + i] * bp[i];
        }
        float b0 = bs[0];
#pragma unroll
        for (int t = 0; t < 4; t++) {
            int fsv = fsrc[t], fdv = fdst[t];
            s_fs[t] = fsv;
            s_fd[t] = fdv;
            s_vs[t] = fsv ? make_float4(vps[0], vps[1], vps[2], vps[3])
                          : make_float4(vas[0], vas[1], vas[2], vas[3]);
            s_vd[t] = fdv ? make_float4(vpd[0], vpd[1], vpd[2], vpd[3])
                          : make_float4(vad[0], vad[1], vad[2], vad[3]);
            s_c[t]  = b0 + (fsv ? cps : cas) + (fdv ? cpd : cad);
        }
    }
    __syncthreads();

    int i = blockIdx.x * blockDim.x + threadIdx.x;
    int base = i * 4;
    if (base + 3 < E) {
        int4 s4 = __ldcs(reinterpret_cast<const int4*>(src) + i);
        int4 d4 = __ldcs(reinterpret_cast<const int4*>(dst) + i);
        int4 t4 = __ldcs(reinterpret_cast<const int4*>(typ) + i);

        int se[4] = {s4.x, s4.y, s4.z, s4.w};
        int de[4] = {d4.x, d4.y, d4.z, d4.w};
        int te[4] = {t4.x, t4.y, t4.z, t4.w};

        float r[4];
#pragma unroll
        for (int pair = 0; pair < 2; pair++) {
            int k0 = pair * 2, k1 = k0 + 1;
            int t0 = te[k0], t1 = te[k1];
            // Address path: scalar flag LDS + register SEL only (no LDS of
            // pointers/vectors before the gathers issue).
            const float4* sp0 = s_fs[t0] ? px : ax;
            const float4* dp0 = s_fd[t0] ? px : ax;
            const float4* sp1 = s_fs[t1] ? px : ax;
            const float4* dp1 = s_fd[t1] ? px : ax;
            // 4 gathers in flight.
            float4 sf0 = __ldg(sp0 + se[k0]);
            float4 df0 = __ldg(dp0 + de[k0]);
            float4 sf1 = __ldg(sp1 + se[k1]);
            float4 df1 = __ldg(dp1 + de[k1]);
            // Consume path: vectors fetched from smem AFTER gathers return;
            // LDS latency overlaps the gather wait, costs no extra regs.
            float4 v;
            float acc0, acc1;
            v = s_vs[t0];
            acc0  = sf0.x * v.x + sf0.y * v.y + sf0.z * v.z + sf0.w * v.w;
            v = s_vd[t0];
            acc0 += df0.x * v.x + df0.y * v.y + df0.z * v.z + df0.w * v.w;
            v = s_vs[t1];
            acc1  = sf1.x * v.x + sf1.y * v.y + sf1.z * v.z + sf1.w * v.w;
            v = s_vd[t1];
            acc1 += df1.x * v.x + df1.y * v.y + df1.z * v.z + df1.w * v.w;
            r[k0] = acc0 + s_c[t0];
            r[k1] = acc1 + s_c[t1];
        }

        __stcs(reinterpret_cast<float4*>(out) + i,
               make_float4(r[0], r[1], r[2], r[3]));
    } else if (base < E) {
        for (int e = base; e < E; e++) {
            int t = typ[e];
            const float4* sb = s_fs[t] ? px : ax;
            const float4* db = s_fd[t] ? px : ax;
            float4 sf = __ldg(sb + src[e]);
            float4 df = __ldg(db + dst[e]);
            float4 vs = s_vs[t];
            float4 vd = s_vd[t];
            out[e] = sf.x * vs.x + sf.y * vs.y + sf.z * vs.z + sf.w * vs.w
                   + df.x * vd.x + df.y * vd.y + df.z * vd.z + df.w * vd.w
                   + s_c[t];
        }
    }
}

extern "C" void kernel_launch(void* const* d_in, const int* in_sizes, int n_in,
                              void* d_out, int out_size)
{
    const float* author_x = (const float*)d_in[0];
    const float* paper_x  = (const float*)d_in[1];
    const int*   src      = (const int*)  d_in[2];
    const int*   dst      = (const int*)  d_in[3];
    const int*   typ      = (const int*)  d_in[4];
    const int*   fsrc     = (const int*)  d_in[5];
    const int*   fdst     = (const int*)  d_in[6];
    const float* Wa       = (const float*)d_in[7];
    const float* ba       = (const float*)d_in[8];
    const float* Wp       = (const float*)d_in[9];
    const float* bp       = (const float*)d_in[10];
    const float* Ws       = (const float*)d_in[11];
    const float* bs       = (const float*)d_in[12];

    int E = in_sizes[2];
    int quads = (E + 3) / 4;
    int eb = (quads + 255) / 256;
    fused_k<<<eb, 256>>>((const float4*)author_x, (const float4*)paper_x,
                         src, dst, typ, (float*)d_out, E,
                         Wa, ba, Wp, bp, Ws, bs, fsrc, fdst);
}